// round 2
// baseline (speedup 1.0000x reference)
#include <cuda_runtime.h>
#include <cuda_fp16.h>
#include <cstdint>

#define BATCH   8192
#define OBS     21
#define HID     512
#define OVERALL 5632
#define IN_DIM  5653
#define OUT_DIM 5640
#define ACT     8

// ---------------- packed weight scratch (device globals; no allocs) ----------------
__device__ __align__(16) __half g_Wb0[512 * 32];          // block0: 512 out x 21->32 k (zero padded)
__device__ __align__(16) __half g_Wb [10 * 512 * 512];    // blocks 1..10: [j][n][k]
__device__ __align__(16) float  g_WmT[512 * 8];           // mean block transposed [k][a]
__device__ __align__(16) float  g_WlT[5664 * 8];          // logstd transposed, padded [c][a]

// ---------------- prep: pack banded blocks, convert to fp16 ----------------
__global__ void prep_kernel(const float* __restrict__ Wm, const float* __restrict__ Wl)
{
    int idx = blockIdx.x * 256 + threadIdx.x;
    if (idx < 512 * 32) {
        int n = idx >> 5, k = idx & 31;
        g_Wb0[idx] = __float2half_rn(k < OBS ? Wm[n * IN_DIM + k] : 0.f);
        return;
    }
    idx -= 512 * 32;
    if (idx < 10 * 512 * 512) {
        int j   = idx >> 18;
        int rem = idx & 262143;
        int n   = rem >> 9, k = rem & 511;
        g_Wb[idx] = __float2half_rn(Wm[(size_t)(512 * (j + 1) + n) * IN_DIM + (OBS + 512 * j + k)]);
        return;
    }
    idx -= 10 * 512 * 512;
    if (idx < 512 * 8) {
        int k = idx >> 3, a = idx & 7;
        g_WmT[idx] = Wm[(size_t)(OVERALL + a) * IN_DIM + (IN_DIM - 512) + k];
        return;
    }
    idx -= 512 * 8;
    if (idx < 5664 * 8) {
        int c = idx >> 3, a = idx & 7;
        g_WlT[idx] = (c < IN_DIM) ? Wl[(size_t)a * IN_DIM + c] : 0.f;
    }
}

// ---------------- mma helper ----------------
__device__ __forceinline__ void mma16816(float* c, const uint32_t* a, const uint32_t* b)
{
    asm volatile(
        "mma.sync.aligned.m16n8k16.row.col.f32.f16.f16.f32 "
        "{%0,%1,%2,%3}, {%4,%5,%6,%7}, {%8,%9}, {%0,%1,%2,%3};\n"
        : "+f"(c[0]), "+f"(c[1]), "+f"(c[2]), "+f"(c[3])
        : "r"(a[0]), "r"(a[1]), "r"(a[2]), "r"(a[3]), "r"(b[0]), "r"(b[1]));
}

// ---------------- main banded GEMM: 11 chunks, relu epilogue ----------------
// grid (4 ntiles, 64 mtiles, 11 chunks), 256 threads (8 warps = 2Mx4N of 64x32)
__global__ __launch_bounds__(256) void gemm_kernel(
    const float* __restrict__ obs, const float* __restrict__ hidden0,
    const float* __restrict__ b_mean, float* __restrict__ out_hidden)
{
    const int j    = blockIdx.z;
    const int tid  = threadIdx.x;
    const int warp = tid >> 5, lane = tid & 31;
    const int gid  = lane >> 2, tig = lane & 3;
    const int warpM = warp >> 2, warpN = warp & 3;
    const int mbase = blockIdx.y * 128;
    const int nbase = blockIdx.x * 128;

    __shared__ __half As[2][128][40];
    __shared__ __half Bs[2][128][40];

    float acc[4][4][4];
#pragma unroll
    for (int a = 0; a < 4; a++)
#pragma unroll
        for (int b = 0; b < 4; b++)
#pragma unroll
            for (int e = 0; e < 4; e++) acc[a][b][e] = 0.f;

    const float*  Aptr;
    const __half* Bp;
    int numk, bld;
    if (j == 0) { Aptr = obs;                      numk = 1;  Bp = g_Wb0;                       bld = 32;  }
    else        { Aptr = hidden0 + (j - 1) * 512;  numk = 16; Bp = g_Wb + (size_t)(j - 1) * 512 * 512; bld = 512; }

    const int ac  = (tid & 7) * 4;   // A col (float idx) within 32-wide ktile
    const int ar0 = tid >> 3;        // A row base (+32*i)
    const int bsg = (tid & 3) * 8;   // B col (half idx)
    const int br0 = tid >> 2;        // B row base (+64*i)

    float4 areg[4];
    uint4  breg[2];

    auto loadA = [&](int t) {
        if (j == 0) {
#pragma unroll
            for (int i = 0; i < 4; i++) {
                int r = mbase + ar0 + 32 * i;
                float4 v;
                v.x = (ac + 0 < OBS) ? Aptr[(size_t)r * OBS + ac + 0] : 0.f;
                v.y = (ac + 1 < OBS) ? Aptr[(size_t)r * OBS + ac + 1] : 0.f;
                v.z = (ac + 2 < OBS) ? Aptr[(size_t)r * OBS + ac + 2] : 0.f;
                v.w = (ac + 3 < OBS) ? Aptr[(size_t)r * OBS + ac + 3] : 0.f;
                areg[i] = v;
            }
        } else {
#pragma unroll
            for (int i = 0; i < 4; i++)
                areg[i] = *(const float4*)(Aptr + (size_t)(mbase + ar0 + 32 * i) * OVERALL + t * 32 + ac);
        }
    };
    auto loadB = [&](int t) {
#pragma unroll
        for (int i = 0; i < 2; i++)
            breg[i] = *(const uint4*)(Bp + (size_t)(nbase + br0 + 64 * i) * bld + t * 32 + bsg);
    };
    auto stsA = [&](int buf) {
#pragma unroll
        for (int i = 0; i < 4; i++) {
            __half2* p = (__half2*)&As[buf][ar0 + 32 * i][ac];
            p[0] = __floats2half2_rn(areg[i].x, areg[i].y);
            p[1] = __floats2half2_rn(areg[i].z, areg[i].w);
        }
    };
    auto stsB = [&](int buf) {
#pragma unroll
        for (int i = 0; i < 2; i++)
            *(uint4*)&Bs[buf][br0 + 64 * i][bsg] = breg[i];
    };
    auto compute = [&](int buf) {
#pragma unroll
        for (int kk = 0; kk < 2; kk++) {
            const int kc = kk * 16 + tig * 2;
            uint32_t af[4][4], bf[4][2];
#pragma unroll
            for (int mi = 0; mi < 4; mi++) {
                int r = warpM * 64 + mi * 16 + gid;
                af[mi][0] = *(const uint32_t*)&As[buf][r    ][kc    ];
                af[mi][1] = *(const uint32_t*)&As[buf][r + 8][kc    ];
                af[mi][2] = *(const uint32_t*)&As[buf][r    ][kc + 8];
                af[mi][3] = *(const uint32_t*)&As[buf][r + 8][kc + 8];
            }
#pragma unroll
            for (int ni = 0; ni < 4; ni++) {
                int n = warpN * 32 + ni * 8 + gid;
                bf[ni][0] = *(const uint32_t*)&Bs[buf][n][kc    ];
                bf[ni][1] = *(const uint32_t*)&Bs[buf][n][kc + 8];
            }
#pragma unroll
            for (int mi = 0; mi < 4; mi++)
#pragma unroll
                for (int ni = 0; ni < 4; ni++)
                    mma16816(acc[mi][ni], af[mi], bf[ni]);
        }
    };

    loadA(0); loadB(0);
    stsA(0);  stsB(0);
    __syncthreads();

    int buf = 0;
    for (int t = 0; t < numk; t++) {
        if (t + 1 < numk) { loadA(t + 1); loadB(t + 1); }
        compute(buf);
        if (t + 1 < numk) {
            stsA(buf ^ 1); stsB(buf ^ 1);
            __syncthreads();
            buf ^= 1;
        }
    }

    // epilogue: bias + relu -> new_hidden columns [512*j, 512*j+512)
#pragma unroll
    for (int mi = 0; mi < 4; mi++) {
#pragma unroll
        for (int ni = 0; ni < 4; ni++) {
            int row  = mbase + warpM * 64 + mi * 16 + gid;
            int colw = nbase + warpN * 32 + ni * 8 + tig * 2;
            int colg = j * 512 + colw;
            float bv0 = b_mean[colg], bv1 = b_mean[colg + 1];
            float2 v0, v1;
            v0.x = fmaxf(acc[mi][ni][0] + bv0, 0.f);
            v0.y = fmaxf(acc[mi][ni][1] + bv1, 0.f);
            v1.x = fmaxf(acc[mi][ni][2] + bv0, 0.f);
            v1.y = fmaxf(acc[mi][ni][3] + bv1, 0.f);
            *(float2*)&out_hidden[(size_t)row * OVERALL + colg]       = v0;
            *(float2*)&out_hidden[(size_t)(row + 8) * OVERALL + colg] = v1;
        }
    }
}

// ---------------- tail: new_log_std (K=5653,N=8) + new_mean (K=512,N=8) ----------------
// warp handles 4 batch rows; lanes stride over K; butterfly reduce.
__global__ __launch_bounds__(256) void tail_kernel(
    const float* __restrict__ obs, const float* __restrict__ hidden0,
    const float* __restrict__ b_mean, const float* __restrict__ b_logstd,
    float* __restrict__ out_mean, float* __restrict__ out_logstd)
{
    const int warp = threadIdx.x >> 5, lane = threadIdx.x & 31;
    const int r0 = (blockIdx.x * 8 + warp) * 4;

    float accL[4][8], accM[4][8];
#pragma unroll
    for (int r = 0; r < 4; r++)
#pragma unroll
        for (int a = 0; a < 8; a++) { accL[r][a] = 0.f; accM[r][a] = 0.f; }

    for (int i = 0; i < 177; i++) {
        int c = i * 32 + lane;                        // c < 5664 always (padded)
        const float4* wp = (const float4*)(g_WlT + c * 8);
        float4 w0 = wp[0], w1 = wp[1];

        float xv[4];
#pragma unroll
        for (int r = 0; r < 4; r++) {
            float x = 0.f;
            if (c < OBS)          x = obs[(size_t)(r0 + r) * OBS + c];
            else if (c < IN_DIM)  x = hidden0[(size_t)(r0 + r) * OVERALL + (c - OBS)];
            xv[r] = x;
        }
#pragma unroll
        for (int r = 0; r < 4; r++) {
            accL[r][0] += xv[r] * w0.x; accL[r][1] += xv[r] * w0.y;
            accL[r][2] += xv[r] * w0.z; accL[r][3] += xv[r] * w0.w;
            accL[r][4] += xv[r] * w1.x; accL[r][5] += xv[r] * w1.y;
            accL[r][6] += xv[r] * w1.z; accL[r][7] += xv[r] * w1.w;
        }
        if (c >= IN_DIM - 512 && c < IN_DIM) {
            const float4* mp = (const float4*)(g_WmT + (c - (IN_DIM - 512)) * 8);
            float4 m0 = mp[0], m1 = mp[1];
#pragma unroll
            for (int r = 0; r < 4; r++) {
                accM[r][0] += xv[r] * m0.x; accM[r][1] += xv[r] * m0.y;
                accM[r][2] += xv[r] * m0.z; accM[r][3] += xv[r] * m0.w;
                accM[r][4] += xv[r] * m1.x; accM[r][5] += xv[r] * m1.y;
                accM[r][6] += xv[r] * m1.z; accM[r][7] += xv[r] * m1.w;
            }
        }
    }

#pragma unroll
    for (int r = 0; r < 4; r++)
#pragma unroll
        for (int a = 0; a < 8; a++) {
            float v = accL[r][a];
#pragma unroll
            for (int s = 16; s > 0; s >>= 1) v += __shfl_xor_sync(0xffffffffu, v, s);
            accL[r][a] = v;
            float m = accM[r][a];
#pragma unroll
            for (int s = 16; s > 0; s >>= 1) m += __shfl_xor_sync(0xffffffffu, m, s);
            accM[r][a] = m;
        }

    if (lane == 0) {
#pragma unroll
        for (int r = 0; r < 4; r++)
#pragma unroll
            for (int a = 0; a < 8; a++) {
                out_logstd[(size_t)(r0 + r) * 8 + a] = accL[r][a] + b_logstd[a];
                out_mean  [(size_t)(r0 + r) * 8 + a] = accM[r][a] + b_mean[OVERALL + a];
            }
    }
}

// ---------------- elementwise: prev_mean passthrough + tanh log_std ----------------
__global__ void ew_kernel(const float* __restrict__ pm, const float* __restrict__ pls,
                          float* __restrict__ out_pm, float* __restrict__ out_ls)
{
    int i = blockIdx.x * 256 + threadIdx.x;
    if (i < BATCH * ACT) {
        out_pm[i] = pm[i];
        float t = tanhf(pls[i]);
        out_ls[i] = -5.0f + 3.5f * (t + 1.0f);
    }
}

// ---------------- launch ----------------
extern "C" void kernel_launch(void* const* d_in, const int* in_sizes, int n_in,
                              void* d_out, int out_size)
{
    const float* obs         = (const float*)d_in[0];
    const float* hidden0     = (const float*)d_in[1];
    const float* prev_mean   = (const float*)d_in[2];
    const float* prev_logstd = (const float*)d_in[3];
    const float* W_mean      = (const float*)d_in[4];
    const float* b_mean      = (const float*)d_in[5];
    const float* W_logstd    = (const float*)d_in[6];
    const float* b_logstd    = (const float*)d_in[7];

    float* out   = (float*)d_out;
    float* o_pm  = out;                                   // prev_mean      [8192,8]
    float* o_ls  = out + (size_t)BATCH * ACT;             // log_std        [8192,8]
    float* o_h   = o_ls + (size_t)BATCH * ACT;            // new_hidden     [8192,5632]
    float* o_nm  = o_h + (size_t)BATCH * OVERALL;         // new_mean       [8192,8]
    float* o_nls = o_nm + (size_t)BATCH * ACT;            // new_log_std    [8192,8]

    prep_kernel<<<10497, 256>>>(W_mean, W_logstd);

    dim3 g(4, 64, 11);
    gemm_kernel<<<g, 256>>>(obs, hidden0, b_mean, o_h);

    tail_kernel<<<256, 256>>>(obs, hidden0, b_mean, b_logstd, o_nm, o_nls);
    ew_kernel<<<256, 256>>>(prev_mean, prev_logstd, o_pm, o_ls);
}